// round 15
// baseline (speedup 1.0000x reference)
#include <cuda_runtime.h>
#include <cuda_fp16.h>
#include <math.h>
#include <stdint.h>

// Problem constants
#define BB 4
#define SS 2048
#define DD 1024
#define HH 16
#define HD 64
#define LOG2E 1.4426950408889634f
#define QSCALE_F (0.125f * LOG2E)

// Scratch (__device__ globals per allocation rules)
__device__ __half g_qkv[(size_t)BB * SS * 3 * DD];   // [B,S,3D]; Q slice pre-scaled
__device__ __half g_y[(size_t)BB * SS * DD];         // [B,S,D]
__device__ __half g_xh[(size_t)BB * SS * DD];        // x -> fp16
__device__ __half g_wah[(size_t)DD * 3 * DD];        // W_attn fp16, natural [K][3D]
__device__ __half g_wph[(size_t)DD * DD];            // W_proj fp16, natural [K][D]

__device__ __forceinline__ uint32_t smem_u32(const void* p) {
    uint32_t a;
    asm("{ .reg .u64 t; cvta.to.shared.u64 t, %1; cvt.u32.u64 %0, t; }" : "=r"(a) : "l"(p));
    return a;
}

#define MMA_F16(acc, a0, a1, a2, a3, b0, b1) \
    asm volatile( \
        "mma.sync.aligned.m16n8k16.row.col.f32.f16.f16.f32 " \
        "{%0,%1,%2,%3}, {%4,%5,%6,%7}, {%8,%9}, {%0,%1,%2,%3};" \
        : "+f"((acc)[0]), "+f"((acc)[1]), "+f"((acc)[2]), "+f"((acc)[3]) \
        : "r"(a0), "r"(a1), "r"(a2), "r"(a3), "r"(b0), "r"(b1))

#define LDMX4(r0, r1, r2, r3, addr) \
    asm volatile("ldmatrix.sync.aligned.m8n8.x4.shared.b16 {%0,%1,%2,%3}, [%4];" \
        : "=r"(r0), "=r"(r1), "=r"(r2), "=r"(r3) : "r"(addr))

#define LDMX4T(r0, r1, r2, r3, addr) \
    asm volatile("ldmatrix.sync.aligned.m8n8.x4.trans.shared.b16 {%0,%1,%2,%3}, [%4];" \
        : "=r"(r0), "=r"(r1), "=r"(r2), "=r"(r3) : "r"(addr))

#define CP16(dst, src) \
    asm volatile("cp.async.cg.shared.global [%0], [%1], 16;" :: "r"(dst), "l"(src))
#define CP_COMMIT() asm volatile("cp.async.commit_group;" ::: "memory")
#define CP_WAIT(n)  asm volatile("cp.async.wait_group %0;" :: "n"(n) : "memory")

// ---------------------------------------------------------------------------
// Single fused prep: fp32 -> fp16 for x, W_attn, W_proj (one launch)
// ---------------------------------------------------------------------------
#define N4_X   2097152
#define N4_WA  786432
#define N4_WP  262144
#define N4_ALL (N4_X + N4_WA + N4_WP)   // 3145728

__global__ void cvt_all(const float4* __restrict__ x, __half2* __restrict__ xo,
                        const float4* __restrict__ wa, __half2* __restrict__ wao,
                        const float4* __restrict__ wp, __half2* __restrict__ wpo)
{
    int i = blockIdx.x * blockDim.x + threadIdx.x;
    const float4* in;
    __half2* out;
    int j;
    if (i < N4_X)            { in = x;  out = xo;  j = i; }
    else if (i < N4_X + N4_WA) { in = wa; out = wao; j = i - N4_X; }
    else if (i < N4_ALL)     { in = wp; out = wpo; j = i - N4_X - N4_WA; }
    else return;
    float4 v = in[j];
    out[2 * j]     = __floats2half2_rn(v.x, v.y);
    out[2 * j + 1] = __floats2half2_rn(v.z, v.w);
}

// ---------------------------------------------------------------------------
// FP16 GEMM v4: C[M,Ntot] = A[M,1024] @ W[1024,Ntot] + bias
// CTA 64x128, 128 threads (4 warps, 2m x 2n), warp tile 32x64.
// __launch_bounds__(128,4) -> 4 CTAs/SM, 16 warps/SM; finer wave packing.
// W consumed in NATURAL [K][N] layout via ldmatrix.trans.
// ---------------------------------------------------------------------------
#define GKH 1024
#define KT 32
#define NKT (GKH / KT)          // 32
#define AST 80                  // A row stride (bytes): 64 + 16 pad
#define BSTB 272                // B row stride (bytes): 256 + 16 pad
#define G_AB (64 * AST)         // 5120
#define G_BB (KT * BSTB)        // 8704
#define G_SB (G_AB + G_BB)      // 13824
#define GEMM_SMEM (3 * G_SB)    // 41472

__global__ __launch_bounds__(128, 4) void gemm_f16(
    const __half* __restrict__ A, const __half* __restrict__ W,
    const float* __restrict__ bias, void* __restrict__ Cv,
    int Ntot, int outHalf, int scaleCols)
{
    extern __shared__ char gsm[];
    const uint32_t smb = smem_u32(gsm);

    const int tid = threadIdx.x;
    const int lane = tid & 31;
    const int wid = tid >> 5;          // 0..3
    const int lg = lane >> 2;
    const int lq = lane & 3;
    const int mb = (wid & 1) * 32;     // warp row base (0 or 32)
    const int nbw = (wid >> 1) * 64;   // warp col base (0 or 64)
    const int bn = blockIdx.x;
    const int bm = blockIdx.y;

    const __half* Ag = A + (size_t)(bm * 64) * GKH;
    const __half* Wg = W + bn * 128;

    const int a_lm = (mb + (lane & 15)) * AST + ((lane >> 4) & 1) * 16;
    const int b_lm = ((lane & 7) + ((lane >> 3) & 1) * 8) * BSTB
                   + ((lane >> 4) & 1) * 16 + nbw * 2;

    float acc[2][8][4];
#pragma unroll
    for (int mt = 0; mt < 2; mt++)
#pragma unroll
        for (int nt = 0; nt < 8; nt++)
#pragma unroll
            for (int i = 0; i < 4; i++) acc[mt][nt][i] = 0.0f;

#define G_ISSUE(kt_, st_) do {                                                  \
        const uint32_t sa_ = smb + (st_) * G_SB;                                \
        const uint32_t sb_ = sa_ + G_AB;                                        \
        _Pragma("unroll")                                                       \
        for (int i_ = 0; i_ < 2; i_++) {                                        \
            const int idx_ = tid + i_ * 128;                                    \
            const int row_ = idx_ >> 2;                                         \
            const int c_ = idx_ & 3;                                            \
            CP16(sa_ + row_ * AST + c_ * 16,                                    \
                 Ag + (size_t)row_ * GKH + (kt_) * KT + c_ * 8);                \
        }                                                                       \
        _Pragma("unroll")                                                       \
        for (int i_ = 0; i_ < 4; i_++) {                                        \
            const int idx_ = tid + i_ * 128;                                    \
            const int row_ = idx_ >> 4;                                         \
            const int c_ = idx_ & 15;                                           \
            CP16(sb_ + row_ * BSTB + c_ * 16,                                   \
                 Wg + (size_t)((kt_) * KT + row_) * Ntot + c_ * 8);             \
        }                                                                       \
    } while (0)

    G_ISSUE(0, 0); CP_COMMIT();
    G_ISSUE(1, 1); CP_COMMIT();

    for (int kt = 0; kt < NKT; kt++) {
        CP_WAIT(1);
        __syncthreads();
        if (kt + 2 < NKT) {
            const int st2 = (kt + 2) % 3;
            G_ISSUE(kt + 2, st2);
        }
        CP_COMMIT();

        const int st = kt % 3;
        const uint32_t sa = smb + st * G_SB;
        const uint32_t sb = sa + G_AB;

#pragma unroll
        for (int kb = 0; kb < 2; kb++) {
            uint32_t af[2][4];
#pragma unroll
            for (int mt = 0; mt < 2; mt++)
                LDMX4(af[mt][0], af[mt][1], af[mt][2], af[mt][3],
                      sa + a_lm + mt * 16 * AST + kb * 32);
#pragma unroll
            for (int j = 0; j < 4; j++) {
                uint32_t b0, b1, b2, b3;
                LDMX4T(b0, b1, b2, b3, sb + b_lm + kb * 16 * BSTB + j * 32);
#pragma unroll
                for (int mt = 0; mt < 2; mt++) {
                    MMA_F16(acc[mt][2 * j], af[mt][0], af[mt][1], af[mt][2], af[mt][3], b0, b1);
                    MMA_F16(acc[mt][2 * j + 1], af[mt][0], af[mt][1], af[mt][2], af[mt][3], b2, b3);
                }
            }
        }
    }
#undef G_ISSUE

#pragma unroll
    for (int mt = 0; mt < 2; mt++) {
        const int row0 = bm * 64 + mb + mt * 16 + lg;
#pragma unroll
        for (int nt = 0; nt < 8; nt++) {
            const int col = bn * 128 + nbw + nt * 8 + 2 * lq;
            const float b0 = bias[col], b1 = bias[col + 1];
            float c0 = acc[mt][nt][0] + b0, c1 = acc[mt][nt][1] + b1;
            float c2 = acc[mt][nt][2] + b0, c3 = acc[mt][nt][3] + b1;
            if (outHalf) {
                if (col < scaleCols) {
                    c0 *= QSCALE_F; c1 *= QSCALE_F; c2 *= QSCALE_F; c3 *= QSCALE_F;
                }
                __half* C16 = (__half*)Cv;
                *(__half2*)(C16 + (size_t)row0 * Ntot + col) = __floats2half2_rn(c0, c1);
                *(__half2*)(C16 + (size_t)(row0 + 8) * Ntot + col) = __floats2half2_rn(c2, c3);
            } else {
                float* C = (float*)Cv;
                *(float2*)(C + (size_t)row0 * Ntot + col) = make_float2(c0, c1);
                *(float2*)(C + (size_t)(row0 + 8) * Ntot + col) = make_float2(c2, c3);
            }
        }
    }
}

// ---------------------------------------------------------------------------
// FP16 flash attention (validated round 14: 128 thr, 64-row Q tiles, 3 CTAs/SM).
// ---------------------------------------------------------------------------
#define FSTB 144
#define F_QPB (64 * FSTB)                  // 9216
#define F_KVB (64 * FSTB)                  // 9216
#define F_STGB (2 * F_KVB)                 // 18432
#define FLASH_SMEM (F_QPB + 2 * F_STGB)    // 46080

__global__ __launch_bounds__(128, 3) void flash_f16_kernel(__half* __restrict__ y_out)
{
    extern __shared__ char smc[];
    const uint32_t smb = smem_u32(smc);

    const int tid = threadIdx.x;
    const int wid = tid >> 5;
    const int lane = tid & 31;
    const int lg = lane >> 2;
    const int lq = lane & 3;
    const int mb = wid * 16;

    const int qt = gridDim.x - 1 - blockIdx.x;   // heavy tiles first
    const int h  = blockIdx.y;
    const int b  = blockIdx.z;
    const int q0 = qt * 64;
    const int nchunks = qt + 1;

    const __half* qkv = g_qkv;
    const size_t tokbase = (size_t)b * SS * 3 * DD;

#pragma unroll
    for (int i = 0; i < 4; i++) {
        const int idx = tid + i * 128;
        const int row = idx >> 3;
        const int c = idx & 7;
        CP16(smb + row * FSTB + c * 16,
             qkv + tokbase + (size_t)(q0 + row) * (3 * DD) + h * HD + c * 8);
    }
    CP_COMMIT();

    const int f_row = tid >> 3;
    const int f_c = tid & 7;

#define F_ISSUE(c_, st_) do {                                                    \
        const uint32_t kb_ = smb + F_QPB + (st_) * F_STGB;                       \
        const int k0g_ = (c_) * 64;                                             \
        _Pragma("unroll")                                                        \
        for (int i_ = 0; i_ < 4; i_++) {                                         \
            const int row_ = f_row + i_ * 16;                                    \
            const __half* src_ = qkv + tokbase + (size_t)(k0g_ + row_) * (3 * DD)\
                                 + DD + h * HD + f_c * 8;                        \
            const uint32_t dst_ = kb_ + row_ * FSTB + f_c * 16;                  \
            CP16(dst_, src_);                                                    \
            CP16(dst_ + F_KVB, src_ + DD);                                       \
        }                                                                        \
    } while (0)

    F_ISSUE(0, 0); CP_COMMIT();

    CP_WAIT(1);
    __syncthreads();
    const int a_lm = (mb + (lane & 15)) * FSTB + ((lane >> 4) & 1) * 16;
    uint32_t aq[4][4];
#pragma unroll
    for (int kb = 0; kb < 4; kb++)
        LDMX4(aq[kb][0], aq[kb][1], aq[kb][2], aq[kb][3], smb + a_lm + kb * 32);
    __syncthreads();      // Q region free -> P region

    float o[8][4];
#pragma unroll
    for (int n = 0; n < 8; n++)
#pragma unroll
        for (int i = 0; i < 4; i++) o[n][i] = 0.0f;
    float sum0 = 0.0f, sum1 = 0.0f;

    const int r0g = q0 + mb + lg;
    const int r1g = r0g + 8;

    const int k_lm = ((lane & 7) + ((lane >> 4) & 1) * 8) * FSTB + ((lane >> 3) & 1) * 16;
    const int v_lm = ((lane & 7) + ((lane >> 3) & 1) * 8) * FSTB + ((lane >> 4) & 1) * 16;
    const int p_lm = a_lm;

    for (int c = 0; c < nchunks; c++) {
        const int st = c & 1;
        CP_WAIT(0);
        __syncthreads();
        if (c + 1 < nchunks) F_ISSUE(c + 1, st ^ 1);
        CP_COMMIT();

        const uint32_t ksb = smb + F_QPB + st * F_STGB;
        const uint32_t vsb = ksb + F_KVB;
        const int k0g = c * 64;

        float s[8][4];
#pragma unroll
        for (int n = 0; n < 8; n++)
#pragma unroll
            for (int i = 0; i < 4; i++) s[n][i] = 0.0f;

#pragma unroll
        for (int kb = 0; kb < 4; kb++) {
#pragma unroll
            for (int np = 0; np < 4; np++) {
                uint32_t b0, b1, b2, b3;
                LDMX4(b0, b1, b2, b3, ksb + k_lm + np * 16 * FSTB + kb * 32);
                MMA_F16(s[2 * np], aq[kb][0], aq[kb][1], aq[kb][2], aq[kb][3], b0, b1);
                MMA_F16(s[2 * np + 1], aq[kb][0], aq[kb][1], aq[kb][2], aq[kb][3], b2, b3);
            }
        }

        if (c == qt) {
#pragma unroll
            for (int n = 0; n < 8; n++) {
                const int col = k0g + n * 8 + 2 * lq;
                if (col     > r0g) s[n][0] = -1e30f;
                if (col + 1 > r0g) s[n][1] = -1e30f;
                if (col     > r1g) s[n][2] = -1e30f;
                if (col + 1 > r1g) s[n][3] = -1e30f;
            }
        }

#pragma unroll
        for (int n = 0; n < 8; n++) {
            float p0 = exp2f(s[n][0]);
            float p1 = exp2f(s[n][1]);
            float p2 = exp2f(s[n][2]);
            float p3 = exp2f(s[n][3]);
            sum0 += p0 + p1;
            sum1 += p2 + p3;
            *(__half2*)(smc + (mb + lg) * FSTB + (n * 8 + 2 * lq) * 2) = __floats2half2_rn(p0, p1);
            *(__half2*)(smc + (mb + 8 + lg) * FSTB + (n * 8 + 2 * lq) * 2) = __floats2half2_rn(p2, p3);
        }
        __syncwarp();

#pragma unroll
        for (int kb = 0; kb < 4; kb++) {
            uint32_t ap0, ap1, ap2, ap3;
            LDMX4(ap0, ap1, ap2, ap3, smb + p_lm + kb * 32);
#pragma unroll
            for (int j = 0; j < 4; j++) {
                uint32_t b0, b1, b2, b3;
                LDMX4T(b0, b1, b2, b3, vsb + v_lm + kb * 16 * FSTB + j * 32);
                MMA_F16(o[2 * j], ap0, ap1, ap2, ap3, b0, b1);
                MMA_F16(o[2 * j + 1], ap0, ap1, ap2, ap3, b2, b3);
            }
        }
    }
#undef F_ISSUE

    sum0 += __shfl_xor_sync(0xffffffffu, sum0, 1);
    sum0 += __shfl_xor_sync(0xffffffffu, sum0, 2);
    sum1 += __shfl_xor_sync(0xffffffffu, sum1, 1);
    sum1 += __shfl_xor_sync(0xffffffffu, sum1, 2);
    const float inv0 = 1.0f / sum0;
    const float inv1 = 1.0f / sum1;
#pragma unroll
    for (int n = 0; n < 8; n++) {
        const int col = h * HD + n * 8 + 2 * lq;
        *(__half2*)(y_out + ((size_t)b * SS + r0g) * DD + col) =
            __floats2half2_rn(o[n][0] * inv0, o[n][1] * inv0);
        *(__half2*)(y_out + ((size_t)b * SS + r1g) * DD + col) =
            __floats2half2_rn(o[n][2] * inv1, o[n][3] * inv1);
    }
}

// ---------------------------------------------------------------------------
// Launch
// ---------------------------------------------------------------------------
extern "C" void kernel_launch(void* const* d_in, const int* in_sizes, int n_in,
                              void* d_out, int out_size)
{
    (void)in_sizes; (void)n_in; (void)out_size;
    const float* x      = (const float*)d_in[0];
    const float* W_attn = (const float*)d_in[1];
    const float* b_attn = (const float*)d_in[2];
    const float* W_proj = (const float*)d_in[3];
    const float* b_proj = (const float*)d_in[4];
    float* out = (float*)d_out;

    __half *qkv_p, *y_p, *xh_p, *wah_p, *wph_p;
    cudaGetSymbolAddress((void**)&qkv_p, g_qkv);
    cudaGetSymbolAddress((void**)&y_p, g_y);
    cudaGetSymbolAddress((void**)&xh_p, g_xh);
    cudaGetSymbolAddress((void**)&wah_p, g_wah);
    cudaGetSymbolAddress((void**)&wph_p, g_wph);

    const int M = BB * SS;  // 8192
    cudaFuncSetAttribute(gemm_f16, cudaFuncAttributeMaxDynamicSharedMemorySize, GEMM_SMEM);
    cudaFuncSetAttribute(flash_f16_kernel, cudaFuncAttributeMaxDynamicSharedMemorySize, FLASH_SMEM);

    // 0) Prep: one fused fp32->fp16 cvt for x, W_attn, W_proj
    cvt_all<<<N4_ALL / 256, 256>>>((const float4*)x, (__half2*)xh_p,
                                   (const float4*)W_attn, (__half2*)wah_p,
                                   (const float4*)W_proj, (__half2*)wph_p);
    // 1) QKV projection (fp16 out; Q slice pre-scaled by 0.125*log2e)
    {
        dim3 grid(3 * DD / 128, M / 64);   // 24 x 128 = 3072 CTAs
        gemm_f16<<<grid, 128, GEMM_SMEM>>>(xh_p, wah_p, b_attn, qkv_p, 3 * DD, 1, DD);
    }
    // 2) Causal flash attention (64-row q tiles, 3 CTAs/SM, heavy-first)
    {
        dim3 grid(SS / 64, HH, BB);
        flash_f16_kernel<<<grid, 128, FLASH_SMEM>>>(y_p);
    }
    // 3) Output projection (fp32 out)
    {
        dim3 grid(DD / 128, M / 64);       // 8 x 128 = 1024 CTAs
        gemm_f16<<<grid, 128, GEMM_SMEM>>>(y_p, wph_p, b_proj, out, DD, 0, 0);
    }
}